// round 14
// baseline (speedup 1.0000x reference)
#include <cuda_runtime.h>
#include <math.h>

typedef unsigned long long ull;

#define BSZ    64
#define HD     256
#define ED     512
#define VD     32000
#define NGRP   500          // VD / 64
#define SOS    1
#define EOS    2
#define MAXLEN 48
#define NEG_INF __int_as_float(0xff800000)

// ---------------- persistent device state (k-major: [k][b]) ----------------
__device__ int g_alldone;
__device__ ull g_done;
__device__ int g_tok[BSZ];
__device__ __align__(16) float g_encT[256 * BSZ];
__device__ __align__(16) float g_xT[ED * BSZ];
__device__ __align__(16) float g_hT0[2][HD * BSZ];
__device__ __align__(16) float g_hT1[2][HD * BSZ];
__device__ __align__(16) float g_cT0[HD * BSZ];
__device__ __align__(16) float g_cT1[HD * BSZ];
__device__ float g_pval[NGRP * BSZ];
__device__ int   g_pidx[NGRP * BSZ];

__device__ __forceinline__ float dsig(float x) {
    return (float)(1.0 / (1.0 + exp(-(double)x)));
}
__device__ __forceinline__ float dth(float x) {
    return (float)tanh((double)x);
}

// ================= pre: transpose enc, init tok/flags =================
extern "C" __global__ void k_pre(const float* __restrict__ enc) {
    int b = blockIdx.x, k = threadIdx.x;
    g_encT[k * BSZ + b] = enc[(size_t)b * 256 + k];
    if (b == 0) {
        if (k < BSZ) g_tok[k] = SOS;
        if (k == 0) { g_done = 0ULL; g_alldone = 0; }
    }
}

// ================= init: h_init / c_init =================
// grid 128 x 128 : warp w: which = w>>1 (h vs c), hof = w&1; lane L -> b {2L,2L+1}
extern "C" __global__ void __launch_bounds__(128, 1)
k_init(const float* __restrict__ Wh, const float* __restrict__ bh,
       const float* __restrict__ Wc, const float* __restrict__ bc) {
    int t = threadIdx.x, w = t >> 5, L = t & 31;
    int which = w >> 1, hof = w & 1;
    int h = blockIdx.x * 2 + hof;
    const float* Wr = (which ? Wc : Wh) + (size_t)h * 256;
    float ax = 0.f, ay = 0.f;
#pragma unroll 4
    for (int k = 0; k < 256; k += 4) {
        float4 wv = *(const float4*)(Wr + k);
        float2 x0 = *(const float2*)&g_encT[(k + 0) * BSZ + 2 * L];
        float2 x1 = *(const float2*)&g_encT[(k + 1) * BSZ + 2 * L];
        float2 x2 = *(const float2*)&g_encT[(k + 2) * BSZ + 2 * L];
        float2 x3 = *(const float2*)&g_encT[(k + 3) * BSZ + 2 * L];
        ax = fmaf(wv.x, x0.x, ax); ay = fmaf(wv.x, x0.y, ay);
        ax = fmaf(wv.y, x1.x, ax); ay = fmaf(wv.y, x1.y, ay);
        ax = fmaf(wv.z, x2.x, ax); ay = fmaf(wv.z, x2.y, ay);
        ax = fmaf(wv.w, x3.x, ax); ay = fmaf(wv.w, x3.y, ay);
    }
    float bb = which ? bc[h] : bh[h];
    float2 v = make_float2(ax + bb, ay + bb);
    int idx = h * BSZ + 2 * L;
    if (which == 0) { *(float2*)&g_hT0[0][idx] = v; *(float2*)&g_hT1[0][idx] = v; }
    else            { *(float2*)&g_cT0[idx]    = v; *(float2*)&g_cT1[idx]    = v; }
}

// ================= gather: xT[k][b] = emb[tok[b]][k] =================
extern "C" __global__ void k_gather(const float* __restrict__ emb) {
    int b = blockIdx.x, t = threadIdx.x;
    const float* row = emb + (size_t)g_tok[b] * ED;
    g_xT[t * BSZ + b]         = row[t];
    g_xT[(t + 256) * BSZ + b] = row[t + 256];
}

// ================= LSTM layer =================
// grid 128 x 256 : warp w: gate = w>>1, hof = w&1; lane L -> b {2L,2L+1}
extern "C" __global__ void __launch_bounds__(256, 1)
k_lstm(const float* __restrict__ Wih, const float* __restrict__ Whh,
       const float* __restrict__ bih, const float* __restrict__ bhh,
       int layer, int par) {
    __shared__ float gsm[4][2][BSZ];
    int t = threadIdx.x, w = t >> 5, L = t & 31;
    int gate = w >> 1, hof = w & 1;
    int h = blockIdx.x * 2 + hof;
    int r = gate * HD + h;

    const float* xT; const float* hprev; float* hout; float* cT; int Ei;
    if (layer == 0) { xT = g_xT;           Ei = ED; hprev = g_hT0[par]; hout = g_hT0[par ^ 1]; cT = g_cT0; }
    else            { xT = g_hT0[par ^ 1]; Ei = HD; hprev = g_hT1[par]; hout = g_hT1[par ^ 1]; cT = g_cT1; }

    float ax = 0.f, ay = 0.f;
    const float* Wr = Wih + (size_t)r * Ei;
#pragma unroll 4
    for (int k = 0; k < Ei; k += 4) {
        float4 wv = *(const float4*)(Wr + k);
        float2 x0 = *(const float2*)&xT[(k + 0) * BSZ + 2 * L];
        float2 x1 = *(const float2*)&xT[(k + 1) * BSZ + 2 * L];
        float2 x2 = *(const float2*)&xT[(k + 2) * BSZ + 2 * L];
        float2 x3 = *(const float2*)&xT[(k + 3) * BSZ + 2 * L];
        ax = fmaf(wv.x, x0.x, ax); ay = fmaf(wv.x, x0.y, ay);
        ax = fmaf(wv.y, x1.x, ax); ay = fmaf(wv.y, x1.y, ay);
        ax = fmaf(wv.z, x2.x, ax); ay = fmaf(wv.z, x2.y, ay);
        ax = fmaf(wv.w, x3.x, ax); ay = fmaf(wv.w, x3.y, ay);
    }
    const float* Ur = Whh + (size_t)r * HD;
#pragma unroll 4
    for (int k = 0; k < HD; k += 4) {
        float4 wv = *(const float4*)(Ur + k);
        float2 x0 = *(const float2*)&hprev[(k + 0) * BSZ + 2 * L];
        float2 x1 = *(const float2*)&hprev[(k + 1) * BSZ + 2 * L];
        float2 x2 = *(const float2*)&hprev[(k + 2) * BSZ + 2 * L];
        float2 x3 = *(const float2*)&hprev[(k + 3) * BSZ + 2 * L];
        ax = fmaf(wv.x, x0.x, ax); ay = fmaf(wv.x, x0.y, ay);
        ax = fmaf(wv.y, x1.x, ax); ay = fmaf(wv.y, x1.y, ay);
        ax = fmaf(wv.z, x2.x, ax); ay = fmaf(wv.z, x2.y, ay);
        ax = fmaf(wv.w, x3.x, ax); ay = fmaf(wv.w, x3.y, ay);
    }
    float bb = bih[r] + bhh[r];
    *(float2*)&gsm[gate][hof][2 * L] = make_float2(ax + bb, ay + bb);
    __syncthreads();

    if (t < 128) {
        int ho = t >> 6, b = t & 63;
        int hh = blockIdx.x * 2 + ho;
        float gi = gsm[0][ho][b], gf = gsm[1][ho][b];
        float gg = gsm[2][ho][b], go = gsm[3][ho][b];
        int idx = hh * BSZ + b;
        float c  = cT[idx];
        float cn = dsig(gf) * c + dsig(gi) * dth(gg);
        cT[idx] = cn;
        hout[idx] = dsig(go) * dth(cn);
    }
}

// ================= logits + per-block argmax =================
extern "C" __global__ void __launch_bounds__(256, 1)
k_logits(const float* __restrict__ Wout, const float* __restrict__ bout, int par) {
    __shared__ float h1s[128 * BSZ];     // 32 KB
    __shared__ float redv[8 * BSZ];
    __shared__ int   redi[8 * BSZ];
    int t = threadIdx.x, w = t >> 5, L = t & 31, grp = blockIdx.x;
    const float* h1g = g_hT1[par ^ 1];

    float2 acc[8];
#pragma unroll
    for (int v = 0; v < 8; v++) acc[v] = make_float2(0.f, 0.f);

    for (int half = 0; half < 2; half++) {
        __syncthreads();
        for (int i = t; i < 2048; i += 256)
            ((float4*)h1s)[i] = ((const float4*)(h1g + half * 128 * BSZ))[i];
        __syncthreads();
        const float* wbase = Wout + (size_t)(grp * 64 + w * 8) * HD + half * 128;
#pragma unroll 1
        for (int k4 = 0; k4 < 32; k4++) {
            float4 wv[8];
#pragma unroll
            for (int v = 0; v < 8; v++)
                wv[v] = *(const float4*)(wbase + (size_t)v * HD + k4 * 4);
#pragma unroll
            for (int j = 0; j < 4; j++) {
                float2 hv = *(const float2*)&h1s[(k4 * 4 + j) * BSZ + 2 * L];
#pragma unroll
                for (int v = 0; v < 8; v++) {
                    float wj = (j == 0) ? wv[v].x : (j == 1) ? wv[v].y
                             : (j == 2) ? wv[v].z : wv[v].w;
                    acc[v].x = fmaf(wj, hv.x, acc[v].x);
                    acc[v].y = fmaf(wj, hv.y, acc[v].y);
                }
            }
        }
    }

    int vbase = grp * 64 + w * 8;
    float bvx = NEG_INF, bvy = NEG_INF;
    int bix = 0, biy = 0;
#pragma unroll
    for (int v = 0; v < 8; v++) {
        float bo = bout[vbase + v];
        float sx = acc[v].x + bo, sy = acc[v].y + bo;
        if (sx > bvx) { bvx = sx; bix = vbase + v; }   // ascending idx: '>' keeps first
        if (sy > bvy) { bvy = sy; biy = vbase + v; }
    }
    redv[w * BSZ + 2 * L]     = bvx; redi[w * BSZ + 2 * L]     = bix;
    redv[w * BSZ + 2 * L + 1] = bvy; redi[w * BSZ + 2 * L + 1] = biy;
    __syncthreads();
    if (t < BSZ) {
        float bv = redv[t]; int bi = redi[t];
#pragma unroll
        for (int w2 = 1; w2 < 8; w2++) {
            float v = redv[w2 * BSZ + t]; int i2 = redi[w2 * BSZ + t];
            if (v > bv || (v == bv && i2 < bi)) { bv = v; bi = i2; }
        }
        g_pval[grp * BSZ + t] = bv;
        g_pidx[grp * BSZ + t] = bi;
    }
}

// ================= global argmax + token logic =================
// OUTPUT IS FLOAT32: the harness interprets the 3072-element output buffer as
// float32 (int bit-patterns read as denormals ~0 -> the exact rel_err=1.0
// signature of rounds 3-10). Tokens < 2^24 are exact in fp32.
extern "C" __global__ void __launch_bounds__(256, 1)
k_reduce(float* __restrict__ outp, int step) {
    __shared__ float redv[4 * BSZ];
    __shared__ int   redi[4 * BSZ];
    __shared__ unsigned sball[2];
    int t = threadIdx.x, b = t & 63, q = t >> 6;

    float bv = NEG_INF; int bi = 0x7fffffff;
    for (int p = q * 125; p < q * 125 + 125; p++) {       // 4 * 125 = 500
        float v = g_pval[p * BSZ + b]; int i2 = g_pidx[p * BSZ + b];
        if (v > bv || (v == bv && i2 < bi)) { bv = v; bi = i2; }
    }
    redv[q * BSZ + b] = bv; redi[q * BSZ + b] = bi;
    int adp = g_alldone;                    // previous step's all_done
    ull pdm = g_done;
    __syncthreads();
    if (t < BSZ) {
        bv = redv[t]; bi = redi[t];
#pragma unroll
        for (int q2 = 1; q2 < 4; q2++) {
            float v = redv[q2 * BSZ + t]; int i2 = redi[q2 * BSZ + t];
            if (v > bv || (v == bv && i2 < bi)) { bv = v; bi = i2; }
        }
        int out = adp ? 0 : bi;             // where(all_done, 0, nt)
        outp[t * MAXLEN + step] = (float)out;   // FLOAT32 write
        g_tok[t] = out;
        int nd = (int)((pdm >> t) & 1ULL) | (out == EOS);
        unsigned bal = __ballot_sync(0xffffffffu, nd != 0);
        if ((t & 31) == 0) sball[t >> 5] = bal;
    }
    __syncthreads();
    if (t == 0) {
        ull nm = (ull)sball[0] | ((ull)sball[1] << 32);
        g_done = nm;
        g_alldone = adp | (nm == 0xFFFFFFFFFFFFFFFFULL);
    }
}

// ================= host =================
extern "C" void kernel_launch(void* const* d_in, const int* in_sizes, int n_in,
                              void* d_out, int out_size) {
    (void)in_sizes; (void)n_in; (void)out_size;
    const float* enc  = (const float*)d_in[0];
    const float* emb  = (const float*)d_in[1];
    const float* Wh   = (const float*)d_in[2];
    const float* bh   = (const float*)d_in[3];
    const float* Wc   = (const float*)d_in[4];
    const float* bc   = (const float*)d_in[5];
    const float* Wih0 = (const float*)d_in[6];
    const float* Whh0 = (const float*)d_in[7];
    const float* bih0 = (const float*)d_in[8];
    const float* bhh0 = (const float*)d_in[9];
    const float* Wih1 = (const float*)d_in[10];
    const float* Whh1 = (const float*)d_in[11];
    const float* bih1 = (const float*)d_in[12];
    const float* bhh1 = (const float*)d_in[13];
    const float* Wout = (const float*)d_in[14];
    const float* bout = (const float*)d_in[15];
    float*       outp = (float*)d_out;

    k_pre<<<64, 256>>>(enc);
    k_init<<<128, 128>>>(Wh, bh, Wc, bc);
    for (int s = 0; s < MAXLEN; s++) {
        int par = s & 1;
        k_gather<<<64, 256>>>(emb);
        k_lstm<<<128, 256>>>(Wih0, Whh0, bih0, bhh0, 0, par);
        k_lstm<<<128, 256>>>(Wih1, Whh1, bih1, bhh1, 1, par);
        k_logits<<<NGRP, 256>>>(Wout, bout, par);
        k_reduce<<<1, 256>>>(outp, s);
    }
}